// round 3
// baseline (speedup 1.0000x reference)
#include <cuda_runtime.h>
#include <cuda_bf16.h>

#define NN 100000
#define EE 1600000
#define FF 64

// Scratch: Tx1 and raw A@Tx1 (Chebyshev recurrence folded into GEMM weights).
__device__ __align__(16) float g_t1[NN * FF];
__device__ __align__(16) float g_t2[NN * FF];
__device__ int g_rowptr[NN + 1];

// ---------------------------------------------------------------------------
// Kernel 1: CSR row pointers via binary search (rows is sorted).
// ---------------------------------------------------------------------------
__global__ void build_rowptr(const int* __restrict__ rows) {
    int i = blockIdx.x * blockDim.x + threadIdx.x;
    if (i > NN) return;
    int lo = 0, hi = EE;
    while (lo < hi) {
        int mid = (lo + hi) >> 1;
        if (rows[mid] < i) lo = mid + 1; else hi = mid;
    }
    g_rowptr[i] = lo;
}

// ---------------------------------------------------------------------------
// Kernel 2/3: SPMM, warp per row, float2 per lane, 4-edge unroll (MLP=4).
// PASS 0: src = x (param), dst = g_t1.  PASS 1: src = g_t1, dst = g_t2.
// ---------------------------------------------------------------------------
template <int PASS>
__global__ void spmm_kernel(const float* __restrict__ x,
                            const int* __restrict__ cols,
                            const float* __restrict__ vals) {
    int row = blockIdx.x * 8 + (threadIdx.x >> 5);
    if (row >= NN) return;
    int lane = threadIdx.x & 31;

    const float2* __restrict__ h2 =
        (PASS == 0) ? (const float2*)x : (const float2*)g_t1;
    float2* __restrict__ dst =
        (PASS == 0) ? (float2*)g_t1 : (float2*)g_t2;

    int s = g_rowptr[row];
    int e = g_rowptr[row + 1];

    float accx = 0.f, accy = 0.f;
    int i = s;
    for (; i + 4 <= e; i += 4) {
        int   c0 = cols[i],  c1 = cols[i + 1], c2 = cols[i + 2], c3 = cols[i + 3];
        float v0 = vals[i],  v1 = vals[i + 1], v2 = vals[i + 2], v3 = vals[i + 3];
        float2 a = h2[c0 * 32 + lane];
        float2 b = h2[c1 * 32 + lane];
        float2 c = h2[c2 * 32 + lane];
        float2 d = h2[c3 * 32 + lane];
        accx += v0 * a.x; accy += v0 * a.y;
        accx += v1 * b.x; accy += v1 * b.y;
        accx += v2 * c.x; accy += v2 * c.y;
        accx += v3 * d.x; accy += v3 * d.y;
    }
    for (; i < e; ++i) {
        int   c = cols[i];
        float v = vals[i];
        float2 a = h2[c * 32 + lane];
        accx += v * a.x; accy += v * a.y;
    }
    dst[row * 32 + lane] = make_float2(accx, accy);
}

// ---------------------------------------------------------------------------
// Kernel 4: out = [x | t1 | t2raw] @ [W0-W2 ; W1 ; 2*W2] + bias
// Packed f32x2 FMA GEMM. Block = 128 rows x 64 cols, 256 threads.
// Thread tile: 2 rows x 16 cols (8 f32x2 accumulators per row).
// A read straight from global (L2-hot), weights broadcast from 48KB smem.
// ---------------------------------------------------------------------------
typedef unsigned long long u64t;

// One k-step for both rows: dup scalars, 4x LDS.128 of weights, 16 f32x2 FMA.
#define GEMM_STEP(K, A0S, A1S)                                                \
    {                                                                         \
        u64t d0, d1;                                                          \
        asm("mov.b64 %0, {%1, %1};" : "=l"(d0) : "f"(A0S));                   \
        asm("mov.b64 %0, {%1, %1};" : "=l"(d1) : "f"(A1S));                   \
        const ulonglong2* wp =                                                \
            (const ulonglong2*)&sW[(K) * 64 + cg * 16];                       \
        _Pragma("unroll")                                                     \
        for (int p = 0; p < 4; ++p) {                                         \
            ulonglong2 w = wp[p];                                             \
            asm("fma.rn.f32x2 %0, %1, %2, %0;"                                \
                : "+l"(acc0[2 * p]) : "l"(w.x), "l"(d0));                     \
            asm("fma.rn.f32x2 %0, %1, %2, %0;"                                \
                : "+l"(acc1[2 * p]) : "l"(w.x), "l"(d1));                     \
            asm("fma.rn.f32x2 %0, %1, %2, %0;"                                \
                : "+l"(acc0[2 * p + 1]) : "l"(w.y), "l"(d0));                 \
            asm("fma.rn.f32x2 %0, %1, %2, %0;"                                \
                : "+l"(acc1[2 * p + 1]) : "l"(w.y), "l"(d1));                 \
        }                                                                     \
    }

__global__ void __launch_bounds__(256)
gemm_f32x2_kernel(const float* __restrict__ x,
                  const float* __restrict__ weight,
                  const float* __restrict__ bias,
                  float* __restrict__ out) {
    __shared__ __align__(16) float sW[192 * 64];

    const int tid = threadIdx.x;

    // Stage folded weights: k<64 -> W0-W2 ; k<128 -> W1 ; else -> 2*W2
    for (int idx = tid; idx < 192 * 64; idx += 256) {
        int k = idx >> 6, j = idx & 63;
        float wv;
        if (k < 64)        wv = weight[k * 64 + j] - weight[8192 + k * 64 + j];
        else if (k < 128)  wv = weight[4096 + (k - 64) * 64 + j];
        else               wv = 2.0f * weight[8192 + (k - 128) * 64 + j];
        sW[idx] = wv;
    }
    __syncthreads();

    const int rg = tid >> 2;       // 0..63 row group
    const int cg = tid & 3;        // 0..3  col group (16 cols each)
    const int r0 = blockIdx.x * 128 + rg * 2;
    const int r1 = r0 + 1;
    const int r0c = min(r0, NN - 1);   // clamped for safe loads
    const int r1c = min(r1, NN - 1);

    u64t acc0[8], acc1[8];
#pragma unroll
    for (int p = 0; p < 8; ++p) { acc0[p] = 0ull; acc1[p] = 0ull; }

#pragma unroll
    for (int s = 0; s < 3; ++s) {
        const float4* p0;
        const float4* p1;
        if (s == 0)      { p0 = (const float4*)x    + r0c * 16; p1 = (const float4*)x    + r1c * 16; }
        else if (s == 1) { p0 = (const float4*)g_t1 + r0c * 16; p1 = (const float4*)g_t1 + r1c * 16; }
        else             { p0 = (const float4*)g_t2 + r0c * 16; p1 = (const float4*)g_t2 + r1c * 16; }
        const int kb0 = s * 64;
#pragma unroll 4
        for (int q = 0; q < 16; ++q) {
            float4 a0 = p0[q];
            float4 a1 = p1[q];
            int kb = kb0 + q * 4;
            GEMM_STEP(kb + 0, a0.x, a1.x);
            GEMM_STEP(kb + 1, a0.y, a1.y);
            GEMM_STEP(kb + 2, a0.z, a1.z);
            GEMM_STEP(kb + 3, a0.w, a1.w);
        }
    }

    // Epilogue: unpack, add bias, store as float2.
    float2* out2 = (float2*)out;
#pragma unroll
    for (int p = 0; p < 8; ++p) {
        float2 bb = ((const float2*)bias)[cg * 8 + p];
        float lo, hi;
        asm("mov.b64 {%0, %1}, %2;" : "=f"(lo), "=f"(hi) : "l"(acc0[p]));
        if (r0 < NN)
            out2[r0 * 32 + cg * 8 + p] = make_float2(lo + bb.x, hi + bb.y);
        asm("mov.b64 {%0, %1}, %2;" : "=f"(lo), "=f"(hi) : "l"(acc1[p]));
        if (r1 < NN)
            out2[r1 * 32 + cg * 8 + p] = make_float2(lo + bb.x, hi + bb.y);
    }
}

// ---------------------------------------------------------------------------
extern "C" void kernel_launch(void* const* d_in, const int* in_sizes, int n_in,
                              void* d_out, int out_size) {
    const float* x      = (const float*)d_in[0];
    const int*   rows   = (const int*)d_in[1];
    const int*   cols   = (const int*)d_in[2];
    const float* vals   = (const float*)d_in[3];
    const float* weight = (const float*)d_in[4];
    const float* bias   = (const float*)d_in[5];
    float*       out    = (float*)d_out;

    build_rowptr<<<(NN + 1 + 255) / 256, 256>>>(rows);
    spmm_kernel<0><<<(NN + 7) / 8, 256>>>(x, cols, vals);
    spmm_kernel<1><<<(NN + 7) / 8, 256>>>(x, cols, vals);
    gemm_f32x2_kernel<<<(NN + 127) / 128, 256>>>(x, weight, bias, out);
}

// round 4
// speedup vs baseline: 1.8036x; 1.8036x over previous
#include <cuda_runtime.h>
#include <cuda_bf16.h>

#define NN 100000
#define EE 1600000
#define FF 64

// Scratch: Tx1 and raw A@Tx1 (Chebyshev recurrence folded into GEMM weights).
__device__ __align__(16) float g_t1[NN * FF];
__device__ __align__(16) float g_t2[NN * FF];
__device__ int g_rowptr[NN + 1];

// ---------------------------------------------------------------------------
// Kernel 1: CSR row pointers via binary search (rows is sorted).
// ---------------------------------------------------------------------------
__global__ void build_rowptr(const int* __restrict__ rows) {
    int i = blockIdx.x * blockDim.x + threadIdx.x;
    if (i > NN) return;
    int lo = 0, hi = EE;
    while (lo < hi) {
        int mid = (lo + hi) >> 1;
        if (rows[mid] < i) lo = mid + 1; else hi = mid;
    }
    g_rowptr[i] = lo;
}

// ---------------------------------------------------------------------------
// Kernel 2/3: SPMM, warp per row, float2 per lane, 4-edge unroll (MLP=4).
// PASS 0: src = x (param), dst = g_t1.  PASS 1: src = g_t1, dst = g_t2.
// ---------------------------------------------------------------------------
template <int PASS>
__global__ void spmm_kernel(const float* __restrict__ x,
                            const int* __restrict__ cols,
                            const float* __restrict__ vals) {
    int row = blockIdx.x * 8 + (threadIdx.x >> 5);
    if (row >= NN) return;
    int lane = threadIdx.x & 31;

    const float2* __restrict__ h2 =
        (PASS == 0) ? (const float2*)x : (const float2*)g_t1;
    float2* __restrict__ dst =
        (PASS == 0) ? (float2*)g_t1 : (float2*)g_t2;

    int s = g_rowptr[row];
    int e = g_rowptr[row + 1];

    float accx = 0.f, accy = 0.f;
    int i = s;
    for (; i + 4 <= e; i += 4) {
        int   c0 = cols[i],  c1 = cols[i + 1], c2 = cols[i + 2], c3 = cols[i + 3];
        float v0 = vals[i],  v1 = vals[i + 1], v2 = vals[i + 2], v3 = vals[i + 3];
        float2 a = h2[c0 * 32 + lane];
        float2 b = h2[c1 * 32 + lane];
        float2 c = h2[c2 * 32 + lane];
        float2 d = h2[c3 * 32 + lane];
        accx += v0 * a.x; accy += v0 * a.y;
        accx += v1 * b.x; accy += v1 * b.y;
        accx += v2 * c.x; accy += v2 * c.y;
        accx += v3 * d.x; accy += v3 * d.y;
    }
    for (; i < e; ++i) {
        int   c = cols[i];
        float v = vals[i];
        float2 a = h2[c * 32 + lane];
        accx += v * a.x; accy += v * a.y;
    }
    dst[row * 32 + lane] = make_float2(accx, accy);
}

// ---------------------------------------------------------------------------
// Kernel 4: out = [x | t1 | t2raw] @ [W0-W2 ; W1 ; 2*W2] + bias
// f32x2 GEMM, 8x8 thread tile. Block = 128 rows x 64 cols, 128 threads.
// Weights from smem (2 LDS.128 per warp-k, far under crossbar cap).
// A-operand straight from L2-resident global via float4 (no smem staging).
// ---------------------------------------------------------------------------
typedef unsigned long long u64t;

// One k-step: 2 LDS.128 of weights (4 packed col-pairs), 8 row dups, 32 FMA2.
#define KSTEP(KIDX, COMP)                                                     \
    {                                                                         \
        const ulonglong2* wp = (const ulonglong2*)&sW[(KIDX) * 64 + cg * 8];  \
        ulonglong2 w01 = wp[0];                                               \
        ulonglong2 w23 = wp[1];                                               \
        _Pragma("unroll")                                                     \
        for (int r = 0; r < 8; ++r) {                                         \
            u64t d;                                                           \
            asm("mov.b64 %0, {%1, %1};" : "=l"(d) : "f"(a[r].COMP));          \
            asm("fma.rn.f32x2 %0, %1, %2, %0;" : "+l"(acc[r][0])              \
                : "l"(w01.x), "l"(d));                                        \
            asm("fma.rn.f32x2 %0, %1, %2, %0;" : "+l"(acc[r][1])              \
                : "l"(w01.y), "l"(d));                                        \
            asm("fma.rn.f32x2 %0, %1, %2, %0;" : "+l"(acc[r][2])              \
                : "l"(w23.x), "l"(d));                                        \
            asm("fma.rn.f32x2 %0, %1, %2, %0;" : "+l"(acc[r][3])              \
                : "l"(w23.y), "l"(d));                                        \
        }                                                                     \
    }

__global__ void __launch_bounds__(128, 3)
gemm_f32x2_kernel(const float* __restrict__ x,
                  const float* __restrict__ weight,
                  const float* __restrict__ bias,
                  float* __restrict__ out) {
    __shared__ __align__(16) float sW[192 * 64];

    const int tid = threadIdx.x;

    // Stage folded weights (float4 granularity, 24 iters/thread):
    // k<64 -> W0-W2 ; k<128 -> W1 ; else -> 2*W2
    for (int idx = tid; idx < 192 * 16; idx += 128) {
        int k = idx >> 4;
        int j4 = idx & 15;
        float4 wv;
        if (k < 64) {
            float4 w0 = ((const float4*)weight)[k * 16 + j4];
            float4 w2 = ((const float4*)weight)[2048 + k * 16 + j4];
            wv = make_float4(w0.x - w2.x, w0.y - w2.y, w0.z - w2.z, w0.w - w2.w);
        } else if (k < 128) {
            wv = ((const float4*)weight)[1024 + (k - 64) * 16 + j4];
        } else {
            float4 w2 = ((const float4*)weight)[2048 + (k - 128) * 16 + j4];
            wv = make_float4(2.f * w2.x, 2.f * w2.y, 2.f * w2.z, 2.f * w2.w);
        }
        ((float4*)sW)[idx] = wv;
    }
    __syncthreads();

    const int rg = tid >> 3;   // 0..15: row group of 8
    const int cg = tid & 7;    // 0..7 : col group of 8
    const int row0 = blockIdx.x * 128 + rg * 8;

    u64t acc[8][4];
#pragma unroll
    for (int r = 0; r < 8; ++r)
#pragma unroll
        for (int p = 0; p < 4; ++p) acc[r][p] = 0ull;

#pragma unroll
    for (int s = 0; s < 3; ++s) {
        const float4* src = (s == 0) ? (const float4*)x
                          : (s == 1) ? (const float4*)g_t1
                                     : (const float4*)g_t2;
        const float4* p[8];
#pragma unroll
        for (int r = 0; r < 8; ++r)
            p[r] = src + (size_t)min(row0 + r, NN - 1) * 16;

        const int kb0 = s * 64;
#pragma unroll 2
        for (int q = 0; q < 16; ++q) {
            float4 a[8];
#pragma unroll
            for (int r = 0; r < 8; ++r) a[r] = p[r][q];
            const int kb = kb0 + q * 4;
            KSTEP(kb + 0, x);
            KSTEP(kb + 1, y);
            KSTEP(kb + 2, z);
            KSTEP(kb + 3, w);
        }
    }

    // Epilogue: unpack, add bias, two float4 stores per row.
    float2 bb[4];
#pragma unroll
    for (int p = 0; p < 4; ++p) bb[p] = ((const float2*)bias)[cg * 4 + p];

#pragma unroll
    for (int r = 0; r < 8; ++r) {
        int node = row0 + r;
        if (node < NN) {
            float v[8];
#pragma unroll
            for (int p = 0; p < 4; ++p) {
                float lo, hi;
                asm("mov.b64 {%0, %1}, %2;" : "=f"(lo), "=f"(hi) : "l"(acc[r][p]));
                v[2 * p]     = lo + bb[p].x;
                v[2 * p + 1] = hi + bb[p].y;
            }
            ((float4*)out)[node * 16 + cg * 2]     = make_float4(v[0], v[1], v[2], v[3]);
            ((float4*)out)[node * 16 + cg * 2 + 1] = make_float4(v[4], v[5], v[6], v[7]);
        }
    }
}

// ---------------------------------------------------------------------------
extern "C" void kernel_launch(void* const* d_in, const int* in_sizes, int n_in,
                              void* d_out, int out_size) {
    const float* x      = (const float*)d_in[0];
    const int*   rows   = (const int*)d_in[1];
    const int*   cols   = (const int*)d_in[2];
    const float* vals   = (const float*)d_in[3];
    const float* weight = (const float*)d_in[4];
    const float* bias   = (const float*)d_in[5];
    float*       out    = (float*)d_out;

    build_rowptr<<<(NN + 1 + 255) / 256, 256>>>(rows);
    spmm_kernel<0><<<(NN + 7) / 8, 256>>>(x, cols, vals);
    spmm_kernel<1><<<(NN + 7) / 8, 256>>>(x, cols, vals);
    gemm_f32x2_kernel<<<(NN + 127) / 128, 128>>>(x, weight, bias, out);
}